// round 12
// baseline (speedup 1.0000x reference)
#include <cuda_runtime.h>
#include <cuda_bf16.h>

// RBFEmbedding: out[b,i,d] = token_emb[an[b,i],d] + proj_b[d]
//                          + (1/N) * sum_j sum_k exp(-((d_ij - c_k)/w)^2) * W[k,d]
// B=16, N=512, K=50, D=256. Centers c_k = k*delta, delta = 12/49, w = 2*delta.
//
// Two-kernel scheme:
//  kernel1 (validated, 17.4us): per-(tile, j-slice) partial rbf accumulation,
//           packed double-step recurrence + float2 smem accumulators, S=2.
//  kernel2: sums slice partials + projection epilogue.
// R12 rewrites kernel2's epilogue: W preloaded into 50 registers (k-loop has
// ZERO global loads -- R11 showed it was serialized on LDG W round-trips),
// rbfm read via broadcast LDS.128 (4 loads/k instead of 8), all global
// prefetches issued before the reduce barrier.

#define THREADS 128
#define R 16           // rows (i) per block
#define JG 8           // j-groups (THREADS / R)
#define S 2            // j-slices per tile
#define JSPAN 256      // j's per block (512 / S)
#define JLEN 32        // j's per thread (JSPAN / JG)
#define NS 50
#define KK 25          // 64-bit accumulator slots (2 k each)
#define WIN2 7         // 7 double-steps = 14-center window
#define TILE_F 800     // NS * R floats of partial rbfm per slice

#define THREADS2 256   // kernel2 block size

typedef unsigned long long ull;

__device__ float g_scratch[512 * S * TILE_F];   // 3.3 MB partials

__device__ __forceinline__ ull pack2(float lo, float hi) {
    ull r; asm("mov.b64 %0, {%1, %2};" : "=l"(r) : "f"(lo), "f"(hi)); return r;
}
__device__ __forceinline__ ull pack2u(unsigned lo, unsigned hi) {
    ull r; asm("mov.b64 %0, {%1, %2};" : "=l"(r) : "r"(lo), "r"(hi)); return r;
}
__device__ __forceinline__ void unpack2(ull v, float& lo, float& hi) {
    asm("mov.b64 {%0, %1}, %2;" : "=f"(lo), "=f"(hi) : "l"(v));
}
__device__ __forceinline__ ull add2(ull a, ull b) {
    ull r; asm("add.rn.f32x2 %0, %1, %2;" : "=l"(r) : "l"(a), "l"(b)); return r;
}
__device__ __forceinline__ ull mul2(ull a, ull b) {
    ull r; asm("mul.rn.f32x2 %0, %1, %2;" : "=l"(r) : "l"(a), "l"(b)); return r;
}
__device__ __forceinline__ ull fma2(ull a, ull b, ull c) {
    ull r; asm("fma.rn.f32x2 %0, %1, %2, %3;" : "=l"(r) : "l"(a), "l"(b), "l"(c)); return r;
}

// distance -> (window slot kk0, packed rbf pair rrp, packed ratio pair Gp)
__device__ __forceinline__ void pair_params(
    float xi, float yi, float zi,
    const float* __restrict__ sx, const float* __restrict__ sy,
    const float* __restrict__ sz, int j,
    int& kk0, ull& rrp, ull& Gp)
{
    const float INV_DELTA = 49.0f / 12.0f;
    const float MAGIC     = 12582912.0f;                 // 1.5*2^23
    const float SQL2E     = 1.2011224087864498f;         // sqrt(log2 e)
    const float L2E       = 1.4426950408889634f;
    const float NQL2E     = -0.25f * 1.4426950408889634f;
    const float BETA      = 0.60653065971263342f;        // e^-1/2
    const float BETA2     = 0.36787944117144233f;        // e^-1

    float dx = xi - sx[j];
    float dy = yi - sy[j];
    float dz = zi - sz[j];
    float dd = fmaf(dx, dx, fmaf(dy, dy, fmaf(dz, dz, 1e-8f)));
    float d;  asm("sqrt.approx.f32 %0, %1;" : "=f"(d) : "f"(dd));
    d = fminf(d, 16.0f);

    float t  = d * INV_DELTA;                      // d/delta in [0, 65.4]
    float hf = fmaf(t, 0.5f, -3.5f);               // (t-7)/2
    float hr = __fadd_rn(__fadd_rn(hf, MAGIC), -MAGIC);   // rint
    hr = fminf(fmaxf(hr, 0.0f), 18.0f);            // kk0 in [0,18], k0 = 2*hr
    kk0 = (int)hr;
    float x0 = fmaf(t, 0.5f, -hr);                 // (d - k0*delta)/w

    // rr0 = exp(-x0^2); g0 = exp(x0 - 1/4)
    float u  = x0 * SQL2E;
    float a0 = -(u * u);
    float rr0; asm("ex2.approx.f32 %0, %1;" : "=f"(rr0) : "f"(a0));
    float ga = fmaf(x0, L2E, NQL2E);
    float g0; asm("ex2.approx.f32 %0, %1;" : "=f"(g0) : "f"(ga));

    float g0sq = g0 * g0;
    float gA   = g0sq * BETA;        // g0*g1
    float gB   = gA * BETA2;         // g1*g2
    Gp  = pack2(gA, gB);
    rrp = pack2(rr0, rr0 * g0);      // (rbf_0, rbf_1)
}

// ---- kernel 1: per-slice partial rbf accumulation (unchanged, validated) ----
__global__ __launch_bounds__(THREADS)
void rbf_part_kernel(const float* __restrict__ pos)
{
    __shared__ float sjx[JSPAN], sjy[JSPAN], sjz[JSPAN];   // 3 KB
    __shared__ ull  sacc2[KK][THREADS];                    // 25.6 KB

    const int tid = threadIdx.x;
    const int bx  = blockIdx.x;           // i-tile 0..31
    const int b   = blockIdx.y;           // batch
    const int sl  = blockIdx.z;           // j-slice 0..1
    const int i0  = bx * R;

    const float* pb = pos + (size_t)b * 512 * 3;
    for (int jj = tid; jj < JSPAN; jj += THREADS) {
        const int j = sl * JSPAN + jj;
        sjx[jj] = pb[j * 3 + 0];
        sjy[jj] = pb[j * 3 + 1];
        sjz[jj] = pb[j * 3 + 2];
    }
    #pragma unroll
    for (int kk = 0; kk < KK; ++kk) sacc2[kk][tid] = 0ULL;
    __syncthreads();

    const int r  = tid & (R - 1);
    const int jg = tid >> 4;
    const int ir = i0 + r;
    const float xi = __ldg(&pb[ir * 3 + 0]);
    const float yi = __ldg(&pb[ir * 3 + 1]);
    const float zi = __ldg(&pb[ir * 3 + 2]);

    const ull B4 = pack2(0.13533528323661270f, 0.13533528323661270f); // e^-2
    const int jbase = jg * JLEN;          // local index into sj arrays

    // ---- 2-stage software-pipelined main loop ----
    int kk0; ull rrp, Gp;
    pair_params(xi, yi, zi, sjx, sjy, sjz, jbase, kk0, rrp, Gp);

    #pragma unroll 2
    for (int jj = 0; jj < JLEN - 1; ++jj) {
        int kk0n; ull rrpn, Gpn;
        pair_params(xi, yi, zi, sjx, sjy, sjz, jbase + jj + 1, kk0n, rrpn, Gpn);

        ull* ap = &sacc2[kk0][tid];
        #pragma unroll
        for (int tt = 0; tt < WIN2; ++tt) {
            ap[tt * THREADS] = add2(ap[tt * THREADS], rrp);
            rrp = mul2(rrp, Gp);
            Gp  = mul2(Gp, B4);
        }
        kk0 = kk0n; rrp = rrpn; Gp = Gpn;
    }
    {   // drain
        ull* ap = &sacc2[kk0][tid];
        #pragma unroll
        for (int tt = 0; tt < WIN2; ++tt) {
            ap[tt * THREADS] = add2(ap[tt * THREADS], rrp);
            rrp = mul2(rrp, Gp);
            Gp  = mul2(Gp, B4);
        }
    }
    __syncthreads();

    // ---- reduce JG partials per (k, ii), store slice partial to scratch ----
    const int tile = b * 32 + bx;
    float* dst = g_scratch + ((size_t)tile * S + sl) * TILE_F;
    for (int idx = tid; idx < TILE_F; idx += THREADS) {
        const int k  = idx >> 4;
        const int ii = idx & (R - 1);
        const float* sf = (const float*)&sacc2[k >> 1][0];
        const int par = (k & 1);
        float s = 0.0f;
        #pragma unroll
        for (int g = 0; g < JG; ++g)
            s += sf[(g * R + ii) * 2 + par];
        dst[idx] = s;
    }
}

// ---- kernel 2: sum slice partials + projection epilogue ----
// One d-column per thread. W[*][d0] prefetched into 50 registers before the
// reduce phase (its latency hides the scratch loads); k-loop fully unrolled,
// pure LDS.128 + FFMA2.
__global__ __launch_bounds__(THREADS2)
void rbf_final_kernel(const int* __restrict__ an,
                      const float* __restrict__ tok,
                      const float* __restrict__ W,
                      const float* __restrict__ bias,
                      float* __restrict__ out)
{
    __shared__ __align__(16) ull rbfm2[NS][R / 2];
    __shared__ int an_s[R];

    const int tid = threadIdx.x;
    const int bx  = blockIdx.x;
    const int b   = blockIdx.y;
    const int i0  = bx * R;
    const int tile = b * 32 + bx;
    const int d0  = tid;                   // 0..255

    // ---- prefetch: W column into registers (50 independent LDGs) ----
    float wreg[NS];
    #pragma unroll
    for (int k = 0; k < NS; ++k)
        wreg[k] = __ldg(&W[k * 256 + d0]);
    const float bd = __ldg(&bias[d0]);

    if (tid < R) an_s[tid] = an[b * 512 + i0 + tid];

    // ---- sum S=2 slice partials -> rbfm (overlaps with W prefetch) ----
    const float* src = g_scratch + (size_t)tile * S * TILE_F;
    for (int idx = tid; idx < TILE_F; idx += THREADS2) {
        float s = src[idx] + src[TILE_F + idx];
        ((float*)rbfm2)[idx] = s * (1.0f / 512.0f);
    }
    __syncthreads();

    // ---- token gather + bias ----
    ull acc[8];
    #pragma unroll
    for (int p = 0; p < 8; ++p) {
        acc[p] = pack2(bd + __ldg(&tok[an_s[2 * p] * 256 + d0]),
                       bd + __ldg(&tok[an_s[2 * p + 1] * 256 + d0]));
    }

    // ---- k-loop: zero global loads, 4 broadcast LDS.128 + 8 FFMA2 per k ----
    #pragma unroll
    for (int k = 0; k < NS; ++k) {
        const ull wp = pack2(wreg[k], wreg[k]);
        const uint4* rp4 = (const uint4*)&rbfm2[k][0];
        #pragma unroll
        for (int q = 0; q < 4; ++q) {
            const uint4 v = rp4[q];           // 16B broadcast LDS.128
            acc[2 * q]     = fma2(pack2u(v.x, v.y), wp, acc[2 * q]);
            acc[2 * q + 1] = fma2(pack2u(v.z, v.w), wp, acc[2 * q + 1]);
        }
    }

    float* op = out + ((size_t)(b * 512 + i0)) * 256 + d0;
    #pragma unroll
    for (int p = 0; p < 8; ++p) {
        float lo, hi;
        unpack2(acc[p], lo, hi);
        op[(2 * p) * 256]     = lo;
        op[(2 * p + 1) * 256] = hi;
    }
}

extern "C" void kernel_launch(void* const* d_in, const int* in_sizes, int n_in,
                              void* d_out, int out_size)
{
    const int*   an   = (const int*)  d_in[0];   // [B,512] int32
    const float* pos  = (const float*)d_in[1];   // [B,512,3] f32
    const float* tok  = (const float*)d_in[2];   // [100,256] f32
    const float* W    = (const float*)d_in[3];   // [50,256]  f32
    const float* bias = (const float*)d_in[4];   // [256]     f32

    const int B = in_sizes[0] / 512;             // 16
    dim3 grid1(512 / R, B, S);                   // 32 x 16 x 2 = 1024 blocks
    dim3 grid2(512 / R, B);                      // 512 blocks
    rbf_part_kernel<<<grid1, THREADS>>>(pos);
    rbf_final_kernel<<<grid2, THREADS2>>>(an, tok, W, bias, (float*)d_out);
}

// round 13
// speedup vs baseline: 1.0491x; 1.0491x over previous
#include <cuda_runtime.h>
#include <cuda_bf16.h>

// RBFEmbedding: out[b,i,d] = token_emb[an[b,i],d] + proj_b[d]
//                          + (1/N) * sum_j sum_k exp(-((d_ij - c_k)/w)^2) * W[k,d]
// B=16, N=512, K=50, D=256. Centers c_k = k*delta, delta = 12/49, w = 2*delta.
//
// SINGLE fused kernel (R13). 1024 blocks = (32 i-tiles x 16 b x 2 j-slices);
// each block runs the validated packed double-step recurrence main loop
// (float2 smem accumulators, 2-stage software pipeline) over its 256 j's and
// stores its partial rbf sums to scratch. Last-block-done: the second slice
// block of each tile (detected via per-tile atomic counter, threadfence
// release/acquire) combines both partials IN FIXED SLICE ORDER (deterministic)
// and runs the projection epilogue. Epilogue latency overlaps other tiles'
// main loops; no second kernel launch; partials are L2-hot when re-read.

#define THREADS 128
#define R 16           // rows (i) per block
#define JG 8           // j-groups (THREADS / R)
#define S 2            // j-slices per tile
#define JSPAN 256      // j's per block (512 / S)
#define JLEN 32        // j's per thread (JSPAN / JG)
#define NS 50
#define KK 25          // 64-bit accumulator slots (2 k each)
#define WIN2 7         // 7 double-steps = 14-center window
#define TILE_F 800     // NS * R floats of partial rbfm per slice

typedef unsigned long long ull;

__device__ float g_scratch[512 * S * TILE_F];   // 3.3 MB partials
__device__ int   g_cnt[512];                    // per-tile arrival counters (zero-init)

__device__ __forceinline__ ull pack2(float lo, float hi) {
    ull r; asm("mov.b64 %0, {%1, %2};" : "=l"(r) : "f"(lo), "f"(hi)); return r;
}
__device__ __forceinline__ void unpack2(ull v, float& lo, float& hi) {
    asm("mov.b64 {%0, %1}, %2;" : "=f"(lo), "=f"(hi) : "l"(v));
}
__device__ __forceinline__ ull add2(ull a, ull b) {
    ull r; asm("add.rn.f32x2 %0, %1, %2;" : "=l"(r) : "l"(a), "l"(b)); return r;
}
__device__ __forceinline__ ull mul2(ull a, ull b) {
    ull r; asm("mul.rn.f32x2 %0, %1, %2;" : "=l"(r) : "l"(a), "l"(b)); return r;
}
__device__ __forceinline__ ull fma2(ull a, ull b, ull c) {
    ull r; asm("fma.rn.f32x2 %0, %1, %2, %3;" : "=l"(r) : "l"(a), "l"(b), "l"(c)); return r;
}

// distance -> (window slot kk0, packed rbf pair rrp, packed ratio pair Gp)
__device__ __forceinline__ void pair_params(
    float xi, float yi, float zi,
    const float* __restrict__ sx, const float* __restrict__ sy,
    const float* __restrict__ sz, int j,
    int& kk0, ull& rrp, ull& Gp)
{
    const float INV_DELTA = 49.0f / 12.0f;
    const float MAGIC     = 12582912.0f;                 // 1.5*2^23
    const float SQL2E     = 1.2011224087864498f;         // sqrt(log2 e)
    const float L2E       = 1.4426950408889634f;
    const float NQL2E     = -0.25f * 1.4426950408889634f;
    const float BETA      = 0.60653065971263342f;        // e^-1/2
    const float BETA2     = 0.36787944117144233f;        // e^-1

    float dx = xi - sx[j];
    float dy = yi - sy[j];
    float dz = zi - sz[j];
    float dd = fmaf(dx, dx, fmaf(dy, dy, fmaf(dz, dz, 1e-8f)));
    float d;  asm("sqrt.approx.f32 %0, %1;" : "=f"(d) : "f"(dd));
    d = fminf(d, 16.0f);

    float t  = d * INV_DELTA;                      // d/delta in [0, 65.4]
    float hf = fmaf(t, 0.5f, -3.5f);               // (t-7)/2
    float hr = __fadd_rn(__fadd_rn(hf, MAGIC), -MAGIC);   // rint
    hr = fminf(fmaxf(hr, 0.0f), 18.0f);            // kk0 in [0,18], k0 = 2*hr
    kk0 = (int)hr;
    float x0 = fmaf(t, 0.5f, -hr);                 // (d - k0*delta)/w

    // rr0 = exp(-x0^2); g0 = exp(x0 - 1/4)
    float u  = x0 * SQL2E;
    float a0 = -(u * u);
    float rr0; asm("ex2.approx.f32 %0, %1;" : "=f"(rr0) : "f"(a0));
    float ga = fmaf(x0, L2E, NQL2E);
    float g0; asm("ex2.approx.f32 %0, %1;" : "=f"(g0) : "f"(ga));

    float g0sq = g0 * g0;
    float gA   = g0sq * BETA;        // g0*g1
    float gB   = gA * BETA2;         // g1*g2
    Gp  = pack2(gA, gB);
    rrp = pack2(rr0, rr0 * g0);      // (rbf_0, rbf_1)
}

__global__ __launch_bounds__(THREADS)
void rbf_fused_kernel(const int* __restrict__ an,
                      const float* __restrict__ pos,
                      const float* __restrict__ tok,
                      const float* __restrict__ W,
                      const float* __restrict__ bias,
                      float* __restrict__ out)
{
    __shared__ float sjx[JSPAN], sjy[JSPAN], sjz[JSPAN];   // 3 KB
    __shared__ ull  sacc2[KK][THREADS];                    // 25.6 KB
    __shared__ ull  rbfm2[NS][R / 2];                      // 3.2 KB (epilogue)
    __shared__ int  an_s[R];
    __shared__ int  s_flag;

    const int tid = threadIdx.x;
    const int bx  = blockIdx.x;           // i-tile 0..31
    const int b   = blockIdx.y;           // batch
    const int sl  = blockIdx.z;           // j-slice 0..1
    const int i0  = bx * R;
    const int tile = b * 32 + bx;

    const float* pb = pos + (size_t)b * 512 * 3;
    for (int jj = tid; jj < JSPAN; jj += THREADS) {
        const int j = sl * JSPAN + jj;
        sjx[jj] = pb[j * 3 + 0];
        sjy[jj] = pb[j * 3 + 1];
        sjz[jj] = pb[j * 3 + 2];
    }
    #pragma unroll
    for (int kk = 0; kk < KK; ++kk) sacc2[kk][tid] = 0ULL;
    __syncthreads();

    const int r  = tid & (R - 1);
    const int jg = tid >> 4;
    const int ir = i0 + r;
    const float xi = __ldg(&pb[ir * 3 + 0]);
    const float yi = __ldg(&pb[ir * 3 + 1]);
    const float zi = __ldg(&pb[ir * 3 + 2]);

    const ull B4 = pack2(0.13533528323661270f, 0.13533528323661270f); // e^-2
    const int jbase = jg * JLEN;          // local index into sj arrays

    // ---- 2-stage software-pipelined main loop (validated schedule) ----
    int kk0; ull rrp, Gp;
    pair_params(xi, yi, zi, sjx, sjy, sjz, jbase, kk0, rrp, Gp);

    #pragma unroll 2
    for (int jj = 0; jj < JLEN - 1; ++jj) {
        int kk0n; ull rrpn, Gpn;
        pair_params(xi, yi, zi, sjx, sjy, sjz, jbase + jj + 1, kk0n, rrpn, Gpn);

        ull* ap = &sacc2[kk0][tid];
        #pragma unroll
        for (int tt = 0; tt < WIN2; ++tt) {
            ap[tt * THREADS] = add2(ap[tt * THREADS], rrp);
            rrp = mul2(rrp, Gp);
            Gp  = mul2(Gp, B4);
        }
        kk0 = kk0n; rrp = rrpn; Gp = Gpn;
    }
    {   // drain
        ull* ap = &sacc2[kk0][tid];
        #pragma unroll
        for (int tt = 0; tt < WIN2; ++tt) {
            ap[tt * THREADS] = add2(ap[tt * THREADS], rrp);
            rrp = mul2(rrp, Gp);
            Gp  = mul2(Gp, B4);
        }
    }
    __syncthreads();

    // ---- reduce JG partials per (k, ii), store slice partial to scratch ----
    float* dst = g_scratch + ((size_t)tile * S + sl) * TILE_F;
    for (int idx = tid; idx < TILE_F; idx += THREADS) {
        const int k  = idx >> 4;
        const int ii = idx & (R - 1);
        const float* sf = (const float*)&sacc2[k >> 1][0];
        const int par = (k & 1);
        float s = 0.0f;
        #pragma unroll
        for (int g = 0; g < JG; ++g)
            s += sf[(g * R + ii) * 2 + par];
        dst[idx] = s;
    }

    // ---- last-block-done handoff ----
    __threadfence();             // release: my partial visible GPU-wide
    __syncthreads();             // all threads' stores+fences precede the atomic
    if (tid == 0)
        s_flag = atomicAdd(&g_cnt[tile], 1);
    __syncthreads();
    if (s_flag != S - 1) return; // first arriver exits; last one finishes the tile

    if (tid == 0) g_cnt[tile] = 0;   // reset for next graph replay
    __threadfence();                 // acquire side before reading peer partial
    if (tid < R) an_s[tid] = an[b * 512 + i0 + tid];

    // combine partials in FIXED slice order (deterministic), L2-hot reads
    const float* p0 = g_scratch + (size_t)tile * S * TILE_F;
    for (int idx = tid; idx < TILE_F; idx += THREADS)
        ((float*)rbfm2)[idx] = (p0[idx] + p0[TILE_F + idx]) * (1.0f / 512.0f);
    __syncthreads();

    // ---- epilogue: [16 x 50] @ [50 x 256] + bias + token gather ----
    {
        const int d0 = tid;
        const float bd0 = __ldg(&bias[d0]);
        const float bd1 = __ldg(&bias[d0 + 128]);
        ull accA[8], accB[8];
        #pragma unroll
        for (int p = 0; p < 8; ++p) {
            const int ta = an_s[2 * p] * 256, tb = an_s[2 * p + 1] * 256;
            accA[p] = pack2(bd0 + __ldg(&tok[ta + d0]),       bd0 + __ldg(&tok[tb + d0]));
            accB[p] = pack2(bd1 + __ldg(&tok[ta + d0 + 128]), bd1 + __ldg(&tok[tb + d0 + 128]));
        }
        #pragma unroll 2
        for (int k = 0; k < NS; ++k) {
            const float wa = __ldg(&W[k * 256 + d0]);
            const float wb = __ldg(&W[k * 256 + d0 + 128]);
            const ull wpa = pack2(wa, wa);
            const ull wpb = pack2(wb, wb);
            const ull* rp = rbfm2[k];
            #pragma unroll
            for (int p = 0; p < 8; ++p) {
                const ull rv = rp[p];      // warp-uniform broadcast LDS.64
                accA[p] = fma2(rv, wpa, accA[p]);
                accB[p] = fma2(rv, wpb, accB[p]);
            }
        }
        float* op = out + ((size_t)(b * 512 + i0)) * 256 + d0;
        #pragma unroll
        for (int p = 0; p < 8; ++p) {
            float lo, hi;
            unpack2(accA[p], lo, hi);
            op[(2 * p) * 256]       = lo;
            op[(2 * p + 1) * 256]   = hi;
            unpack2(accB[p], lo, hi);
            op[(2 * p) * 256 + 128]     = lo;
            op[(2 * p + 1) * 256 + 128] = hi;
        }
    }
}

extern "C" void kernel_launch(void* const* d_in, const int* in_sizes, int n_in,
                              void* d_out, int out_size)
{
    const int*   an   = (const int*)  d_in[0];   // [B,512] int32
    const float* pos  = (const float*)d_in[1];   // [B,512,3] f32
    const float* tok  = (const float*)d_in[2];   // [100,256] f32
    const float* W    = (const float*)d_in[3];   // [50,256]  f32
    const float* bias = (const float*)d_in[4];   // [256]     f32

    const int B = in_sizes[0] / 512;             // 16
    dim3 grid(512 / R, B, S);                    // 32 x 16 x 2 = 1024 blocks
    rbf_fused_kernel<<<grid, THREADS>>>(an, pos, tok, W, bias, (float*)d_out);
}